// round 3
// baseline (speedup 1.0000x reference)
#include <cuda_runtime.h>
#include <cuda_bf16.h>
#include <math.h>

// ---------------- constants ----------------
#define PATCH   7
#define HALF    3
#define KNN     5
#define KK      6        // K+1, self included then dropped
#define MAXPTS  65536
#define MAXB    64
#define SORTN   2048

// ---------------- device scratch ----------------
__device__ float g_x[MAXPTS];
__device__ float g_z[MAXPTS];
__device__ float g_h[MAXPTS];
__device__ float g_sq[MAXPTS];
__device__ unsigned char g_valid[MAXPTS];

// sorted-by-x per batch (stride SORTN)
__device__ float gs_x[MAXB * SORTN];
__device__ float gs_z[MAXB * SORTN];
__device__ float gs_h[MAXB * SORTN];
__device__ float gs_q[MAXB * SORTN];

__device__ int   g_validn[MAXB];
__device__ float g_Sh[MAXB];
__device__ float g_Sls[MAXB];
__device__ float g_Ssl[MAXB];

// [0]=sum(sc) [1]=sum(ydiff*sc) [2]=sum(ydiff) [3]=sum(w) [4]=sum(diff*w) [5]=sum(sl1*w)
__device__ float g_acc[8];
__device__ int   g_cnt;

// ---------------- helpers ----------------
__device__ __forceinline__ float smooth_l1f(float x, float y, float beta) {
    float d = fabsf(x - y);
    return d < beta ? 0.5f * d * d / beta : d - 0.5f * beta;
}

__device__ __forceinline__ float bilinear_ref(const float* __restrict__ im,
                                              float x, float y, int W, int H) {
    x = fminf(fmaxf(x, 0.f), (float)(W - 1));
    y = fminf(fmaxf(y, 0.f), (float)(H - 1));
    float x0 = floorf(x), y0 = floorf(y);
    float fx = x - x0, fy = y - y0;
    int x0i = min(max((int)x0, 0), W - 1);
    int x1i = min(x0i + 1, W - 1);
    int y0i = min(max((int)y0, 0), H - 1);
    int y1i = min(y0i + 1, H - 1);
    float v00 = __ldg(im + (size_t)y0i * W + x0i);
    float v01 = __ldg(im + (size_t)y0i * W + x1i);
    float v10 = __ldg(im + (size_t)y1i * W + x0i);
    float v11 = __ldg(im + (size_t)y1i * W + x1i);
    float top = v00 * (1.f - fx) + v01 * fx;
    float bot = v10 * (1.f - fx) + v11 * fx;
    return top * (1.f - fy) + bot * fy;
}

__device__ __forceinline__ void sample_pair(const float* __restrict__ im,
                                            float cx, float cy, int W, int H,
                                            int lane, float& t0, float& t1) {
    float fix = floorf(cx), fiy = floorf(cy);
    float fx = cx - fix, fy = cy - fiy;
    int ix = (int)fix, iy = (int)fiy;
    int r = lane >> 2, cg = (lane & 3) << 1;
    bool fast = (ix >= 3) && (ix + 4 <= W - 1) && (iy >= 3) && (iy + 4 <= H - 1);
    if (fast) {
        const float* rp = im + (size_t)(iy - 3 + r) * W + (ix - 3 + cg);
        float w0 = __ldg(rp);
        float w1 = __ldg(rp + 1);
        float w2 = __shfl_down_sync(0xffffffffu, w0, 1);
        float ci0 = fmaf(fx, w1 - w0, w0);
        float ci1 = fmaf(fx, w2 - w1, w1);
        float cj0 = __shfl_down_sync(0xffffffffu, ci0, 4);
        float cj1 = __shfl_down_sync(0xffffffffu, ci1, 4);
        t0 = fmaf(fy, cj0 - ci0, ci0);
        t1 = fmaf(fy, cj1 - ci1, ci1);
    } else {
        t0 = bilinear_ref(im, cx + (float)(cg - 3), cy + (float)(r - 3), W, H);
        t1 = bilinear_ref(im, cx + (float)(cg - 2), cy + (float)(r - 3), W, H);
    }
}

// ---------------- kernel 0: zero accumulators ----------------
__global__ void zero_kernel() {
    int t = threadIdx.x;
    if (t < 8)   g_acc[t] = 0.f;
    if (t == 8)  g_cnt = 0;
    if (t < MAXB) {
        g_validn[t] = 0;
        g_Sh[t] = 0.f;
        g_Sls[t] = 0.f;
        g_Ssl[t] = 0.f;
    }
}

// ---------------- kernel 1: per-point photo + geometry (unchanged, validated) ----------------
__global__ void point_kernel(const float* __restrict__ lg,
                             const float* __restrict__ rg,
                             const float* __restrict__ kpl,
                             const float* __restrict__ kpr,
                             const float* __restrict__ scores,
                             const float* __restrict__ Q,
                             int B, int N, int H, int W) {
    __shared__ float sacc[6];
    __shared__ int   scnt;
    int tid  = threadIdx.x;
    int warp = tid >> 5;
    int lane = tid & 31;
    if (tid < 6) sacc[tid] = 0.f;
    if (tid == 6) scnt = 0;
    __syncthreads();

    int total = B * N;
    int p = blockIdx.x * 8 + warp;
    if (p < total) {
        int b = p / N;
        float klx = __ldg(kpl + 2 * p),  kly = __ldg(kpl + 2 * p + 1);
        float krx = __ldg(kpr + 2 * p),  kry = __ldg(kpr + 2 * p + 1);
        float sc  = __ldg(scores + p);

        const float* Qb = Q + (size_t)b * 16;
        float disp = klx - krx;
        float p0 = Qb[0]  * klx + Qb[1]  * kly + Qb[2]  * disp + Qb[3];
        float p1 = Qb[4]  * klx + Qb[5]  * kly + Qb[6]  * disp + Qb[7];
        float p2 = Qb[8]  * klx + Qb[9]  * kly + Qb[10] * disp + Qb[11];
        float p3 = Qb[12] * klx + Qb[13] * kly + Qb[14] * disp + Qb[15];
        float Wc = fmaxf(p3, 1e-6f);
        float X = p0 / Wc, Y = p1 / Wc, Z = p2 / Wc;
        bool  valid = (Z > 100.f) && (Z < 30000.f) && (sc > 0.1f);
        float pmx = X / 1000.f;
        float hh  = Y / 1000.f;
        float pmz = Z / 1000.f;
        float sq  = pmx * pmx + pmz * pmz;

        if (lane == 0) {
            g_h[p]     = hh;
            g_valid[p] = valid ? 1 : 0;
            if (valid) { g_x[p] = pmx; g_z[p] = pmz; g_sq[p] = sq; }
            else       { g_x[p] = 0.f; g_z[p] = 0.f; g_sq[p] = 4e18f; }
        }

        const float* L = lg + (size_t)b * H * W;
        const float* R = rg + (size_t)b * H * W;
        float tl0, tl1, tr0, tr1;
        sample_pair(L, klx, kly, W, H, lane, tl0, tl1);
        sample_pair(R, krx, kry, W, H, lane, tr0, tr1);

        int r = lane >> 2;
        float a = 0.f;
        if (r < 7) {
            a = fabsf(tl0 - tr0);
            if ((lane & 3) < 3) a += fabsf(tl1 - tr1);
        }
        #pragma unroll
        for (int o = 16; o > 0; o >>= 1)
            a += __shfl_down_sync(0xffffffffu, a, o);

        float cl = __shfl_sync(0xffffffffu, tl1, 13);
        float cr = __shfl_sync(0xffffffffu, tr1, 13);

        if (lane == 0) {
            float diffm = a / 49.f;
            float isb   = (cl > 0.02f) ? 1.f : 0.f;
            float w     = sc * isb;
            float ydiff = fabsf(kly - kry);
            atomicAdd(&sacc[0], sc);
            atomicAdd(&sacc[1], ydiff * sc);
            atomicAdd(&sacc[2], ydiff);
            atomicAdd(&sacc[3], w);
            atomicAdd(&sacc[4], diffm * w);
            atomicAdd(&sacc[5], smooth_l1f(cl, cr, 1.f) * w);
            if (sc > 0.1f) atomicAdd(&scnt, 1);
            if (valid) {
                atomicAdd(&g_validn[b], 1);
                atomicAdd(&g_Sh[b], hh);
            }
        }
    }
    __syncthreads();
    if (tid < 6) atomicAdd(&g_acc[tid], sacc[tid]);
    if (tid == 6 && scnt) atomicAdd(&g_cnt, scnt);
}

// ---------------- kernel 2a: per-batch bitonic sort by x ----------------
// one block per batch, 1024 threads; valid points first (key = x), invalid 1e30, pad 3e30
__global__ void sort_kernel(int N) {
    __shared__ float key[SORTN];
    __shared__ int   sidx[SORTN];
    int b = blockIdx.x;
    int tid = threadIdx.x;

    for (int i = tid; i < SORTN; i += 1024) {
        if (i < N) {
            int p = b * N + i;
            key[i]  = g_valid[p] ? g_x[p] : 1e30f;
            sidx[i] = i;
        } else { key[i] = 3e30f; sidx[i] = 0; }
    }
    __syncthreads();

    for (int k = 2; k <= SORTN; k <<= 1) {
        for (int j = k >> 1; j > 0; j >>= 1) {
            for (int i = tid; i < SORTN; i += 1024) {
                int ixj = i ^ j;
                if (ixj > i) {
                    float a = key[i], c = key[ixj];
                    bool up = ((i & k) == 0);
                    if ((a > c) == up) {
                        key[i] = c; key[ixj] = a;
                        int t = sidx[i]; sidx[i] = sidx[ixj]; sidx[ixj] = t;
                    }
                }
            }
            __syncthreads();
        }
    }

    for (int i = tid; i < SORTN; i += 1024) {
        int o = b * SORTN + i;
        if (i < N) {
            int p = b * N + sidx[i];
            gs_x[o] = key[i];
            gs_z[o] = g_z[p];
            gs_h[o] = g_h[p];
            gs_q[o] = g_sq[p];
        } else {
            gs_x[o] = 3e30f; gs_z[o] = 0.f; gs_h[o] = 0.f; gs_q[o] = 4e18f;
        }
    }
}

// ---------------- kernel 2b: windowed 6-NN over x-sorted points ----------------
__global__ void knn_sorted_kernel(int B, int N) {
    __shared__ float sx[SORTN], sz[SORTN], sh[SORTN], sq[SORTN];
    __shared__ float sls, ssl;
    int b   = blockIdx.y;
    int tid = threadIdx.x;      // 256
    int n   = blockIdx.x * 256 + tid;
    int base = b * SORTN;

    for (int i = tid; i < SORTN; i += 256) {
        sx[i] = gs_x[base + i];
        sz[i] = gs_z[base + i];
        sh[i] = gs_h[base + i];
        sq[i] = gs_q[base + i];
    }
    if (tid == 0) { sls = 0.f; ssl = 0.f; }
    __syncthreads();

    int nv = g_validn[b];
    bool active = (n < nv) && (n < N);

    float ls = 0.f, pensum = 0.f;
    if (active) {
        float xn = sx[n], zn = sz[n], hn = sh[n], sqn = sq[n];

        float d2k[KK], hk[KK];
        #pragma unroll
        for (int k = 0; k < KK; k++) { d2k[k] = 3.4e38f; hk[k] = 0.f; }

        // insert self (same formula as neighbors for consistency)
        {
            float d2 = sqn + sqn - 2.f * (xn * xn + zn * zn);
            d2k[KK - 1] = d2; hk[KK - 1] = hn;
            #pragma unroll
            for (int k = KK - 1; k > 0; k--) {
                if (d2k[k] < d2k[k - 1]) {
                    float td = d2k[k]; d2k[k] = d2k[k - 1]; d2k[k - 1] = td;
                    float th = hk[k];  hk[k]  = hk[k - 1];  hk[k - 1]  = th;
                }
            }
        }

        int l = n - 1, r = n + 1;
        while (true) {
            float dl = (l >= 0)     ? (xn - sx[l]) : 4e30f;
            float dr = (r < SORTN)  ? (sx[r] - xn) : 4e30f;
            bool left = (dl <= dr);
            float dx = left ? dl : dr;
            if (dx > 1e29f) break;                                     // exhausted / sentinels
            if (dx * dx > d2k[KK - 1] * 1.0001f + 1e-9f) break;        // no closer candidate possible
            int j = left ? l : r;
            float d2 = sqn + sq[j] - 2.f * (xn * sx[j] + zn * sz[j]);  // EXACT validated expression
            if (d2 < d2k[KK - 1]) {
                d2k[KK - 1] = d2; hk[KK - 1] = sh[j];
                #pragma unroll
                for (int k = KK - 1; k > 0; k--) {
                    if (d2k[k] < d2k[k - 1]) {
                        float td = d2k[k]; d2k[k] = d2k[k - 1]; d2k[k - 1] = td;
                        float th = hk[k];  hk[k]  = hk[k - 1];  hk[k - 1]  = th;
                    }
                }
            }
            if (left) l--; else r++;
        }

        // d2k sorted ascending; [0] = self. Neighbors are 1..5.
        float lm = (hk[1] + hk[2] + hk[3] + hk[4] + hk[5]) / 5.f;
        ls = smooth_l1f(hn, lm, 0.01f);
        #pragma unroll
        for (int k = 1; k < KK; k++) {
            float nd = fmaxf(sqrtf(fmaxf(d2k[k], 1e-12f)), 0.001f);
            float s  = fabsf(hk[k] - hn) / nd;
            pensum  += fmaxf(s - 0.4f, 0.f);
        }
    }

    #pragma unroll
    for (int o = 16; o > 0; o >>= 1) {
        ls     += __shfl_down_sync(0xffffffffu, ls, o);
        pensum += __shfl_down_sync(0xffffffffu, pensum, o);
    }
    if ((tid & 31) == 0) {
        atomicAdd(&sls, ls);
        atomicAdd(&ssl, pensum);
    }
    __syncthreads();
    if (tid == 0) {
        atomicAdd(&g_Sls[b], sls);
        atomicAdd(&g_Ssl[b], ssl);
    }
}

// ---------------- fallback brute-force knn (N > SORTN only) ----------------
__global__ void knn_brute_kernel(int B, int N) {
    __shared__ float4 tile[256];
    __shared__ float  sls, ssl;
    int b = blockIdx.y;
    int n = blockIdx.x * blockDim.x + threadIdx.x;
    int rowBase = b * N;

    bool active = false;
    float xn = 0.f, zn = 0.f, sqn = 0.f, hn = 0.f;
    if (n < N) {
        int p = rowBase + n;
        active = (g_valid[p] != 0);
        xn = g_x[p]; zn = g_z[p]; sqn = g_sq[p]; hn = g_h[p];
    }
    float d2k[KK], hk[KK];
    #pragma unroll
    for (int k = 0; k < KK; k++) { d2k[k] = 3.4e38f; hk[k] = 0.f; }
    if (threadIdx.x == 0) { sls = 0.f; ssl = 0.f; }

    for (int basem = 0; basem < N; basem += 256) {
        int m = basem + threadIdx.x;
        if (m < N) {
            int q = rowBase + m;
            tile[threadIdx.x] = make_float4(g_x[q], g_z[q], g_h[q], g_sq[q]);
        }
        __syncthreads();
        int cnt = min(256, N - basem);
        if (active) {
            for (int j = 0; j < cnt; j++) {
                float4 v = tile[j];
                float d2 = sqn + v.w - 2.f * (xn * v.x + zn * v.y);
                if (d2 < d2k[KK - 1]) {
                    d2k[KK - 1] = d2; hk[KK - 1] = v.z;
                    #pragma unroll
                    for (int k = KK - 1; k > 0; k--) {
                        if (d2k[k] < d2k[k - 1]) {
                            float td = d2k[k]; d2k[k] = d2k[k - 1]; d2k[k - 1] = td;
                            float th = hk[k];  hk[k]  = hk[k - 1];  hk[k - 1]  = th;
                        }
                    }
                }
            }
        }
        __syncthreads();
    }

    float ls = 0.f, pensum = 0.f;
    if (active) {
        float lm = (hk[1] + hk[2] + hk[3] + hk[4] + hk[5]) / 5.f;
        ls = smooth_l1f(hn, lm, 0.01f);
        #pragma unroll
        for (int k = 1; k < KK; k++) {
            float nd = fmaxf(sqrtf(fmaxf(d2k[k], 1e-12f)), 0.001f);
            float s  = fabsf(hk[k] - hn) / nd;
            pensum  += fmaxf(s - 0.4f, 0.f);
        }
    }
    #pragma unroll
    for (int o = 16; o > 0; o >>= 1) {
        ls     += __shfl_down_sync(0xffffffffu, ls, o);
        pensum += __shfl_down_sync(0xffffffffu, pensum, o);
    }
    if ((threadIdx.x & 31) == 0) { atomicAdd(&sls, ls); atomicAdd(&ssl, pensum); }
    __syncthreads();
    if (threadIdx.x == 0) { atomicAdd(&g_Sls[b], sls); atomicAdd(&g_Ssl[b], ssl); }
}

// ---------------- kernel 3: finalize ----------------
__global__ void final_kernel(float* __restrict__ out, int B, int N) {
    int t = threadIdx.x;
    float s_ls = 0.f, s_sl = 0.f, s_lz = 0.f, s_ok = 0.f;
    for (int b = t; b < B; b += 32) {
        int nvi  = g_validn[b];
        float nv = (float)max(nvi, 1);
        float ok = (nvi >= 10) ? 1.f : 0.f;
        s_ls += ok * (g_Sls[b] / nv);
        s_sl += ok * (g_Ssl[b] / (nv * (float)KNN));
        s_lz += ok * fabsf(g_Sh[b] / nv);
        s_ok += ok;
    }
    #pragma unroll
    for (int o = 16; o > 0; o >>= 1) {
        s_ls += __shfl_down_sync(0xffffffffu, s_ls, o);
        s_sl += __shfl_down_sync(0xffffffffu, s_sl, o);
        s_lz += __shfl_down_sync(0xffffffffu, s_lz, o);
        s_ok += __shfl_down_sync(0xffffffffu, s_ok, o);
    }
    if (t == 0) {
        float ws = g_acc[0];
        float l_epi = (ws > 0.0001f) ? (g_acc[1] / fmaxf(ws, 1e-12f))
                                     : (g_acc[2] / (float)(B * N));
        float wsum = g_acc[3];
        float safe = fmaxf(wsum, 1e-12f);
        float l_masked    = (wsum > 0.0001f) ? (g_acc[4] / safe) : 0.f;
        float l_intensity = (wsum > 0.0001f) ? (g_acc[5] / safe) : 0.f;

        float nb = fmaxf(s_ok, 1.f);
        bool gate = (g_cnt >= 10) && (s_ok > 0.f);

        out[0] = l_masked + l_intensity;
        out[1] = l_epi;
        out[2] = gate ? (s_ls / nb) : 0.f;
        out[3] = gate ? (s_sl / nb) : 0.f;
        out[4] = gate ? (s_lz / nb) : 0.f;
    }
}

// ---------------- launch ----------------
extern "C" void kernel_launch(void* const* d_in, const int* in_sizes, int n_in,
                              void* d_out, int out_size) {
    const float* lg     = (const float*)d_in[0];
    const float* rg     = (const float*)d_in[1];
    const float* kpl    = (const float*)d_in[2];
    const float* kpr    = (const float*)d_in[3];
    const float* scores = (const float*)d_in[4];
    const float* Q      = (const float*)d_in[5];
    float* out = (float*)d_out;

    int B = in_sizes[5] / 16;
    int N = in_sizes[4] / B;
    int HW = in_sizes[0] / B;
    int W = 1280, H = HW / W;
    if (H * W != HW) { W = 1280; H = HW / W; }
    int total = B * N;

    zero_kernel<<<1, 256>>>();

    int blocks1 = (total + 7) / 8;
    point_kernel<<<blocks1, 256>>>(lg, rg, kpl, kpr, scores, Q, B, N, H, W);

    if (N <= SORTN && B <= MAXB) {
        sort_kernel<<<B, 1024>>>(N);
        dim3 g2((N + 255) / 256, B);
        knn_sorted_kernel<<<g2, 256>>>(B, N);
    } else {
        dim3 g2((N + 255) / 256, B);
        knn_brute_kernel<<<g2, 256>>>(B, N);
    }

    final_kernel<<<1, 32>>>(out, B, N);
}

// round 5
// speedup vs baseline: 1.8508x; 1.8508x over previous
#include <cuda_runtime.h>
#include <cuda_bf16.h>
#include <math.h>

// ---------------- constants ----------------
#define KNN     5
#define KK      6        // K+1, self included then dropped
#define MAXPTS  65536
#define MAXB    64
#define SORTN   2048
#define WIN     64       // window half-width in sorted order

// ---------------- device scratch ----------------
__device__ float g_x[MAXPTS];
__device__ float g_z[MAXPTS];
__device__ float g_h[MAXPTS];
__device__ float g_sq[MAXPTS];
__device__ unsigned char g_valid[MAXPTS];

// sorted-by-x per batch (stride SORTN)
__device__ float gs_x[MAXB * SORTN];
__device__ float gs_z[MAXB * SORTN];
__device__ float gs_h[MAXB * SORTN];
__device__ float gs_q[MAXB * SORTN];

__device__ int   g_nflag[MAXB];
__device__ int   g_flag[MAXB * SORTN];

__device__ int   g_validn[MAXB];
__device__ float g_Sh[MAXB];
__device__ float g_Sls[MAXB];
__device__ float g_Ssl[MAXB];

// [0]=sum(sc) [1]=sum(ydiff*sc) [2]=sum(ydiff) [3]=sum(w) [4]=sum(diff*w) [5]=sum(sl1*w)
__device__ float g_acc[8];
__device__ int   g_cnt;

// ---------------- helpers ----------------
__device__ __forceinline__ float smooth_l1f(float x, float y, float beta) {
    float d = fabsf(x - y);
    return d < beta ? 0.5f * d * d / beta : d - 0.5f * beta;
}

__device__ __forceinline__ float bilinear_ref(const float* __restrict__ im,
                                              float x, float y, int W, int H) {
    x = fminf(fmaxf(x, 0.f), (float)(W - 1));
    y = fminf(fmaxf(y, 0.f), (float)(H - 1));
    float x0 = floorf(x), y0 = floorf(y);
    float fx = x - x0, fy = y - y0;
    int x0i = min(max((int)x0, 0), W - 1);
    int x1i = min(x0i + 1, W - 1);
    int y0i = min(max((int)y0, 0), H - 1);
    int y1i = min(y0i + 1, H - 1);
    float v00 = __ldg(im + (size_t)y0i * W + x0i);
    float v01 = __ldg(im + (size_t)y0i * W + x1i);
    float v10 = __ldg(im + (size_t)y1i * W + x0i);
    float v11 = __ldg(im + (size_t)y1i * W + x1i);
    float top = v00 * (1.f - fx) + v01 * fx;
    float bot = v10 * (1.f - fx) + v11 * fx;
    return top * (1.f - fy) + bot * fy;
}

__device__ __forceinline__ void sample_pair(const float* __restrict__ im,
                                            float cx, float cy, int W, int H,
                                            int lane, float& t0, float& t1) {
    float fix = floorf(cx), fiy = floorf(cy);
    float fx = cx - fix, fy = cy - fiy;
    int ix = (int)fix, iy = (int)fiy;
    int r = lane >> 2, cg = (lane & 3) << 1;
    bool fast = (ix >= 3) && (ix + 4 <= W - 1) && (iy >= 3) && (iy + 4 <= H - 1);
    if (fast) {
        const float* rp = im + (size_t)(iy - 3 + r) * W + (ix - 3 + cg);
        float w0 = __ldg(rp);
        float w1 = __ldg(rp + 1);
        float w2 = __shfl_down_sync(0xffffffffu, w0, 1);
        float ci0 = fmaf(fx, w1 - w0, w0);
        float ci1 = fmaf(fx, w2 - w1, w1);
        float cj0 = __shfl_down_sync(0xffffffffu, ci0, 4);
        float cj1 = __shfl_down_sync(0xffffffffu, ci1, 4);
        t0 = fmaf(fy, cj0 - ci0, ci0);
        t1 = fmaf(fy, cj1 - ci1, ci1);
    } else {
        t0 = bilinear_ref(im, cx + (float)(cg - 3), cy + (float)(r - 3), W, H);
        t1 = bilinear_ref(im, cx + (float)(cg - 2), cy + (float)(r - 3), W, H);
    }
}

// sorted-insert (ascending) into static-indexed 6-lists
#define INSERT6(d2, hv)                                                     \
    if ((d2) < d2k[KK - 1]) {                                               \
        d2k[KK - 1] = (d2); hk[KK - 1] = (hv);                              \
        _Pragma("unroll")                                                   \
        for (int _k = KK - 1; _k > 0; _k--) {                               \
            if (d2k[_k] < d2k[_k - 1]) {                                    \
                float _td = d2k[_k]; d2k[_k] = d2k[_k-1]; d2k[_k-1] = _td;  \
                float _th = hk[_k];  hk[_k]  = hk[_k-1];  hk[_k-1]  = _th;  \
            }                                                               \
        }                                                                   \
    }

// ---------------- kernel 0: zero accumulators ----------------
__global__ void zero_kernel() {
    int t = threadIdx.x;
    if (t < 8)   g_acc[t] = 0.f;
    if (t == 8)  g_cnt = 0;
    if (t < MAXB) {
        g_validn[t] = 0;
        g_nflag[t]  = 0;
        g_Sh[t] = 0.f;
        g_Sls[t] = 0.f;
        g_Ssl[t] = 0.f;
    }
}

// ---------------- kernel 1: per-point photo + geometry ----------------
__global__ void point_kernel(const float* __restrict__ lg,
                             const float* __restrict__ rg,
                             const float* __restrict__ kpl,
                             const float* __restrict__ kpr,
                             const float* __restrict__ scores,
                             const float* __restrict__ Q,
                             int B, int N, int H, int W) {
    __shared__ float sacc[6];
    __shared__ int   scnt;
    __shared__ float sVh;
    __shared__ int   sVn;
    int tid  = threadIdx.x;
    int warp = tid >> 5;
    int lane = tid & 31;
    if (tid < 6) sacc[tid] = 0.f;
    if (tid == 6) scnt = 0;
    if (tid == 7) { sVh = 0.f; sVn = 0; }
    __syncthreads();

    int total = B * N;
    int pFirst = blockIdx.x * 8;
    bool oneBatch = (pFirst / N) == (min(pFirst + 7, total - 1) / N);
    int p = pFirst + warp;
    if (p < total) {
        int b = p / N;
        float klx = __ldg(kpl + 2 * p),  kly = __ldg(kpl + 2 * p + 1);
        float krx = __ldg(kpr + 2 * p),  kry = __ldg(kpr + 2 * p + 1);
        float sc  = __ldg(scores + p);

        const float* Qb = Q + (size_t)b * 16;
        float disp = klx - krx;
        float p0 = Qb[0]  * klx + Qb[1]  * kly + Qb[2]  * disp + Qb[3];
        float p1 = Qb[4]  * klx + Qb[5]  * kly + Qb[6]  * disp + Qb[7];
        float p2 = Qb[8]  * klx + Qb[9]  * kly + Qb[10] * disp + Qb[11];
        float p3 = Qb[12] * klx + Qb[13] * kly + Qb[14] * disp + Qb[15];
        float Wc = fmaxf(p3, 1e-6f);
        float X = p0 / Wc, Y = p1 / Wc, Z = p2 / Wc;
        bool  valid = (Z > 100.f) && (Z < 30000.f) && (sc > 0.1f);
        float pmx = X / 1000.f;
        float hh  = Y / 1000.f;
        float pmz = Z / 1000.f;
        float sq  = pmx * pmx + pmz * pmz;

        if (lane == 0) {
            g_h[p]     = hh;
            g_valid[p] = valid ? 1 : 0;
            if (valid) { g_x[p] = pmx; g_z[p] = pmz; g_sq[p] = sq; }
            else       { g_x[p] = 0.f; g_z[p] = 0.f; g_sq[p] = 4e18f; }
        }

        const float* L = lg + (size_t)b * H * W;
        const float* R = rg + (size_t)b * H * W;
        float tl0, tl1, tr0, tr1;
        sample_pair(L, klx, kly, W, H, lane, tl0, tl1);
        sample_pair(R, krx, kry, W, H, lane, tr0, tr1);

        int r = lane >> 2;
        float a = 0.f;
        if (r < 7) {
            a = fabsf(tl0 - tr0);
            if ((lane & 3) < 3) a += fabsf(tl1 - tr1);
        }
        #pragma unroll
        for (int o = 16; o > 0; o >>= 1)
            a += __shfl_down_sync(0xffffffffu, a, o);

        float cl = __shfl_sync(0xffffffffu, tl1, 13);
        float cr = __shfl_sync(0xffffffffu, tr1, 13);

        if (lane == 0) {
            float diffm = a / 49.f;
            float isb   = (cl > 0.02f) ? 1.f : 0.f;
            float w     = sc * isb;
            float ydiff = fabsf(kly - kry);
            atomicAdd(&sacc[0], sc);
            atomicAdd(&sacc[1], ydiff * sc);
            atomicAdd(&sacc[2], ydiff);
            atomicAdd(&sacc[3], w);
            atomicAdd(&sacc[4], diffm * w);
            atomicAdd(&sacc[5], smooth_l1f(cl, cr, 1.f) * w);
            if (sc > 0.1f) atomicAdd(&scnt, 1);
            if (valid) {
                if (oneBatch) {
                    atomicAdd(&sVn, 1);
                    atomicAdd(&sVh, hh);
                } else {
                    atomicAdd(&g_validn[b], 1);
                    atomicAdd(&g_Sh[b], hh);
                }
            }
        }
    }
    __syncthreads();
    if (tid < 6) atomicAdd(&g_acc[tid], sacc[tid]);
    if (tid == 6 && scnt) atomicAdd(&g_cnt, scnt);
    if (tid == 7 && oneBatch && sVn) {
        int b0 = pFirst / N;
        atomicAdd(&g_validn[b0], sVn);
        atomicAdd(&g_Sh[b0], sVh);
    }
}

// ---------------- kernel 2a: per-batch bitonic sort by x ----------------
__global__ void sort_kernel(int N) {
    __shared__ float key[SORTN];
    __shared__ int   sidx[SORTN];
    int b = blockIdx.x;
    int tid = threadIdx.x;

    for (int i = tid; i < SORTN; i += 1024) {
        if (i < N) {
            int p = b * N + i;
            key[i]  = g_valid[p] ? g_x[p] : 1e30f;
            sidx[i] = i;
        } else { key[i] = 3e30f; sidx[i] = 0; }
    }
    __syncthreads();

    for (int k = 2; k <= SORTN; k <<= 1) {
        for (int j = k >> 1; j > 0; j >>= 1) {
            for (int i = tid; i < SORTN; i += 1024) {
                int ixj = i ^ j;
                if (ixj > i) {
                    float a = key[i], c = key[ixj];
                    bool up = ((i & k) == 0);
                    if ((a > c) == up) {
                        key[i] = c; key[ixj] = a;
                        int t = sidx[i]; sidx[i] = sidx[ixj]; sidx[ixj] = t;
                    }
                }
            }
            __syncthreads();
        }
    }

    for (int i = tid; i < SORTN; i += 1024) {
        int o = b * SORTN + i;
        if (i < N) {
            int p = b * N + sidx[i];
            gs_x[o] = key[i];
            gs_z[o] = g_z[p];
            gs_h[o] = g_h[p];
            gs_q[o] = g_sq[p];
        } else {
            gs_x[o] = 3e30f; gs_z[o] = 0.f; gs_h[o] = 0.f; gs_q[o] = 4e18f;
        }
    }
}

// ---------------- kernel 2b: fixed-window 6-NN over x-sorted VALID prefix ----------------
__global__ void knn_window_kernel(int B, int N) {
    __shared__ float sx[SORTN], sz[SORTN], sh[SORTN], sq[SORTN];
    __shared__ float sls, ssl;
    int b   = blockIdx.y;
    int tid = threadIdx.x;      // 256
    int n   = blockIdx.x * 256 + tid;
    int base = b * SORTN;

    int nv = g_validn[b];
    for (int i = tid; i < nv; i += 256) {
        sx[i] = gs_x[base + i];
        sz[i] = gs_z[base + i];
        sh[i] = gs_h[base + i];
        sq[i] = gs_q[base + i];
    }
    if (tid == 0) { sls = 0.f; ssl = 0.f; }
    __syncthreads();

    bool active = (n < nv);

    float ls = 0.f, pensum = 0.f;
    if (active) {
        float xn = sx[n], zn = sz[n], hn = sh[n], sqn = sq[n];

        float d2k[KK], hk[KK];
        #pragma unroll
        for (int k = 0; k < KK; k++) { d2k[k] = 3.4e38f; hk[k] = 0.f; }

        // window clamped to the VALID prefix [0, nv)
        int lo = n - WIN;
        int hi = n + WIN;
        if (lo < 0)  { hi -= lo; lo = 0; }
        if (hi > nv) { lo -= (hi - nv); hi = nv; if (lo < 0) lo = 0; }

        #pragma unroll 4
        for (int j = lo; j < hi; j++) {
            float d2 = sqn + sq[j] - 2.f * (xn * sx[j] + zn * sz[j]);
            INSERT6(d2, sh[j]);
        }

        // exactness check within valid prefix only
        float thr = d2k[KK - 1] * 1.0001f + 1e-9f;
        bool bad = false;
        if (lo > 0)  { float dx = xn - sx[lo - 1]; if (dx * dx <= thr) bad = true; }
        if (hi < nv) { float dx = sx[hi] - xn;     if (dx * dx <= thr) bad = true; }

        if (bad) {
            int slot = atomicAdd(&g_nflag[b], 1);
            g_flag[base + slot] = n;
        } else {
            float lm = (hk[1] + hk[2] + hk[3] + hk[4] + hk[5]) / 5.f;
            ls = smooth_l1f(hn, lm, 0.01f);
            #pragma unroll
            for (int k = 1; k < KK; k++) {
                float nd = fmaxf(sqrtf(fmaxf(d2k[k], 1e-12f)), 0.001f);
                float s  = fabsf(hk[k] - hn) / nd;
                pensum  += fmaxf(s - 0.4f, 0.f);
            }
        }
    }

    #pragma unroll
    for (int o = 16; o > 0; o >>= 1) {
        ls     += __shfl_down_sync(0xffffffffu, ls, o);
        pensum += __shfl_down_sync(0xffffffffu, pensum, o);
    }
    if ((tid & 31) == 0) {
        atomicAdd(&sls, ls);
        atomicAdd(&ssl, pensum);
    }
    __syncthreads();
    if (tid == 0) {
        atomicAdd(&g_Sls[b], sls);
        atomicAdd(&g_Ssl[b], ssl);
    }
}

// ---------------- kernel 2c: exact brute fallback for flagged points ----------------
// warp per flagged point; lane-strided scan over VALID prefix; warp merge.
__global__ void knn_flag_kernel(int B, int N) {
    __shared__ float sls, ssl;
    int b    = blockIdx.y;
    int tid  = threadIdx.x;        // 256 = 8 warps
    int lane = tid & 31;
    int wIdx = blockIdx.x * 8 + (tid >> 5);
    int warpsPerBatch = gridDim.x * 8;
    int base = b * SORTN;
    int nf = g_nflag[b];
    int nv = g_validn[b];

    if (tid == 0) { sls = 0.f; ssl = 0.f; }
    __syncthreads();

    float lsAcc = 0.f, penAcc = 0.f;
    for (int f = wIdx; f < nf; f += warpsPerBatch) {
        int n = g_flag[base + f];
        float xn = gs_x[base + n], zn = gs_z[base + n];
        float hn = gs_h[base + n], sqn = gs_q[base + n];

        float d2k[KK], hk[KK];
        #pragma unroll
        for (int k = 0; k < KK; k++) { d2k[k] = 3.4e38f; hk[k] = 0.f; }

        for (int j = lane; j < nv; j += 32) {
            float d2 = sqn + __ldg(gs_q + base + j)
                     - 2.f * (xn * __ldg(gs_x + base + j) + zn * __ldg(gs_z + base + j));
            float hv = __ldg(gs_h + base + j);
            INSERT6(d2, hv);
        }

        // warp merge: extract 6 global minima from 32 sorted per-lane lists
        float md[KK], mh[KK];
        #pragma unroll
        for (int r = 0; r < KK; r++) {
            float v  = d2k[0];
            float mv = v;
            #pragma unroll
            for (int o = 16; o > 0; o >>= 1)
                mv = fminf(mv, __shfl_xor_sync(0xffffffffu, mv, o));
            unsigned msk = __ballot_sync(0xffffffffu, v == mv);
            int src = __ffs(msk) - 1;
            float hh0 = hk[0];
            float mhh = __shfl_sync(0xffffffffu, hh0, src);
            if (lane == src) {
                #pragma unroll
                for (int k = 0; k < KK - 1; k++) { d2k[k] = d2k[k + 1]; hk[k] = hk[k + 1]; }
                d2k[KK - 1] = 3.4e38f; hk[KK - 1] = 0.f;
            }
            md[r] = mv; mh[r] = mhh;
        }

        if (lane == 0) {
            float lm = (mh[1] + mh[2] + mh[3] + mh[4] + mh[5]) / 5.f;
            lsAcc += smooth_l1f(hn, lm, 0.01f);
            #pragma unroll
            for (int k = 1; k < KK; k++) {
                float nd = fmaxf(sqrtf(fmaxf(md[k], 1e-12f)), 0.001f);
                float s  = fabsf(mh[k] - hn) / nd;
                penAcc  += fmaxf(s - 0.4f, 0.f);
            }
        }
    }
    if (lane == 0 && (lsAcc != 0.f || penAcc != 0.f)) {
        atomicAdd(&sls, lsAcc);
        atomicAdd(&ssl, penAcc);
    }
    __syncthreads();
    if (tid == 0 && (sls != 0.f || ssl != 0.f)) {
        atomicAdd(&g_Sls[b], sls);
        atomicAdd(&g_Ssl[b], ssl);
    }
}

// ---------------- fallback brute-force knn (N > SORTN only) ----------------
__global__ void knn_brute_kernel(int B, int N) {
    __shared__ float4 tile[256];
    __shared__ float  sls, ssl;
    int b = blockIdx.y;
    int n = blockIdx.x * blockDim.x + threadIdx.x;
    int rowBase = b * N;

    bool active = false;
    float xn = 0.f, zn = 0.f, sqn = 0.f, hn = 0.f;
    if (n < N) {
        int p = rowBase + n;
        active = (g_valid[p] != 0);
        xn = g_x[p]; zn = g_z[p]; sqn = g_sq[p]; hn = g_h[p];
    }
    float d2k[KK], hk[KK];
    #pragma unroll
    for (int k = 0; k < KK; k++) { d2k[k] = 3.4e38f; hk[k] = 0.f; }
    if (threadIdx.x == 0) { sls = 0.f; ssl = 0.f; }

    for (int basem = 0; basem < N; basem += 256) {
        int m = basem + threadIdx.x;
        if (m < N) {
            int q = rowBase + m;
            tile[threadIdx.x] = make_float4(g_x[q], g_z[q], g_h[q], g_sq[q]);
        }
        __syncthreads();
        int cnt = min(256, N - basem);
        if (active) {
            for (int j = 0; j < cnt; j++) {
                float4 v = tile[j];
                float d2 = sqn + v.w - 2.f * (xn * v.x + zn * v.y);
                INSERT6(d2, v.z);
            }
        }
        __syncthreads();
    }

    float ls = 0.f, pensum = 0.f;
    if (active) {
        float lm = (hk[1] + hk[2] + hk[3] + hk[4] + hk[5]) / 5.f;
        ls = smooth_l1f(hn, lm, 0.01f);
        #pragma unroll
        for (int k = 1; k < KK; k++) {
            float nd = fmaxf(sqrtf(fmaxf(d2k[k], 1e-12f)), 0.001f);
            float s  = fabsf(hk[k] - hn) / nd;
            pensum  += fmaxf(s - 0.4f, 0.f);
        }
    }
    #pragma unroll
    for (int o = 16; o > 0; o >>= 1) {
        ls     += __shfl_down_sync(0xffffffffu, ls, o);
        pensum += __shfl_down_sync(0xffffffffu, pensum, o);
    }
    if ((threadIdx.x & 31) == 0) { atomicAdd(&sls, ls); atomicAdd(&ssl, pensum); }
    __syncthreads();
    if (threadIdx.x == 0) { atomicAdd(&g_Sls[b], sls); atomicAdd(&g_Ssl[b], ssl); }
}

// ---------------- kernel 3: finalize ----------------
__global__ void final_kernel(float* __restrict__ out, int B, int N) {
    int t = threadIdx.x;
    float s_ls = 0.f, s_sl = 0.f, s_lz = 0.f, s_ok = 0.f;
    for (int b = t; b < B; b += 32) {
        int nvi  = g_validn[b];
        float nv = (float)max(nvi, 1);
        float ok = (nvi >= 10) ? 1.f : 0.f;
        s_ls += ok * (g_Sls[b] / nv);
        s_sl += ok * (g_Ssl[b] / (nv * (float)KNN));
        s_lz += ok * fabsf(g_Sh[b] / nv);
        s_ok += ok;
    }
    #pragma unroll
    for (int o = 16; o > 0; o >>= 1) {
        s_ls += __shfl_down_sync(0xffffffffu, s_ls, o);
        s_sl += __shfl_down_sync(0xffffffffu, s_sl, o);
        s_lz += __shfl_down_sync(0xffffffffu, s_lz, o);
        s_ok += __shfl_down_sync(0xffffffffu, s_ok, o);
    }
    if (t == 0) {
        float ws = g_acc[0];
        float l_epi = (ws > 0.0001f) ? (g_acc[1] / fmaxf(ws, 1e-12f))
                                     : (g_acc[2] / (float)(B * N));
        float wsum = g_acc[3];
        float safe = fmaxf(wsum, 1e-12f);
        float l_masked    = (wsum > 0.0001f) ? (g_acc[4] / safe) : 0.f;
        float l_intensity = (wsum > 0.0001f) ? (g_acc[5] / safe) : 0.f;

        float nb = fmaxf(s_ok, 1.f);
        bool gate = (g_cnt >= 10) && (s_ok > 0.f);

        out[0] = l_masked + l_intensity;
        out[1] = l_epi;
        out[2] = gate ? (s_ls / nb) : 0.f;
        out[3] = gate ? (s_sl / nb) : 0.f;
        out[4] = gate ? (s_lz / nb) : 0.f;
    }
}

// ---------------- launch ----------------
extern "C" void kernel_launch(void* const* d_in, const int* in_sizes, int n_in,
                              void* d_out, int out_size) {
    const float* lg     = (const float*)d_in[0];
    const float* rg     = (const float*)d_in[1];
    const float* kpl    = (const float*)d_in[2];
    const float* kpr    = (const float*)d_in[3];
    const float* scores = (const float*)d_in[4];
    const float* Q      = (const float*)d_in[5];
    float* out = (float*)d_out;

    int B = in_sizes[5] / 16;
    int N = in_sizes[4] / B;
    int HW = in_sizes[0] / B;
    int W = 1280, H = HW / W;
    if (H * W != HW) { W = 1280; H = HW / W; }
    int total = B * N;

    zero_kernel<<<1, 256>>>();

    int blocks1 = (total + 7) / 8;
    point_kernel<<<blocks1, 256>>>(lg, rg, kpl, kpr, scores, Q, B, N, H, W);

    if (N <= SORTN && B <= MAXB) {
        sort_kernel<<<B, 1024>>>(N);
        dim3 g2((N + 255) / 256, B);
        knn_window_kernel<<<g2, 256>>>(B, N);
        dim3 g3(8, B);
        knn_flag_kernel<<<g3, 256>>>(B, N);
    } else {
        dim3 g2((N + 255) / 256, B);
        knn_brute_kernel<<<g2, 256>>>(B, N);
    }

    final_kernel<<<1, 32>>>(out, B, N);
}

// round 6
// speedup vs baseline: 3.2323x; 1.7465x over previous
#include <cuda_runtime.h>
#include <cuda_bf16.h>
#include <math.h>

// ---------------- constants ----------------
#define KNN     5
#define KK      6        // K+1, self included then dropped
#define MAXPTS  65536
#define MAXB    64
#define SORTN   2048
#define WIN     64       // window half-width in sorted order

// ---------------- device scratch ----------------
__device__ float g_x[MAXPTS];
__device__ float g_z[MAXPTS];
__device__ float g_h[MAXPTS];
__device__ float g_sq[MAXPTS];
__device__ unsigned char g_valid[MAXPTS];

// sorted-by-z per batch (stride SORTN)
__device__ float gs_x[MAXB * SORTN];
__device__ float gs_z[MAXB * SORTN];
__device__ float gs_h[MAXB * SORTN];
__device__ float gs_q[MAXB * SORTN];

__device__ int   g_nflag[MAXB];
__device__ int   g_flag[MAXB * SORTN];

__device__ int   g_validn[MAXB];
__device__ float g_Sh[MAXB];
__device__ float g_Sls[MAXB];
__device__ float g_Ssl[MAXB];

// [0]=sum(sc) [1]=sum(ydiff*sc) [2]=sum(ydiff) [3]=sum(w) [4]=sum(diff*w) [5]=sum(sl1*w)
__device__ float g_acc[8];
__device__ int   g_cnt;

// ---------------- helpers ----------------
__device__ __forceinline__ float smooth_l1f(float x, float y, float beta) {
    float d = fabsf(x - y);
    return d < beta ? 0.5f * d * d / beta : d - 0.5f * beta;
}

__device__ __forceinline__ float bilinear_ref(const float* __restrict__ im,
                                              float x, float y, int W, int H) {
    x = fminf(fmaxf(x, 0.f), (float)(W - 1));
    y = fminf(fmaxf(y, 0.f), (float)(H - 1));
    float x0 = floorf(x), y0 = floorf(y);
    float fx = x - x0, fy = y - y0;
    int x0i = min(max((int)x0, 0), W - 1);
    int x1i = min(x0i + 1, W - 1);
    int y0i = min(max((int)y0, 0), H - 1);
    int y1i = min(y0i + 1, H - 1);
    float v00 = __ldg(im + (size_t)y0i * W + x0i);
    float v01 = __ldg(im + (size_t)y0i * W + x1i);
    float v10 = __ldg(im + (size_t)y1i * W + x0i);
    float v11 = __ldg(im + (size_t)y1i * W + x1i);
    float top = v00 * (1.f - fx) + v01 * fx;
    float bot = v10 * (1.f - fx) + v11 * fx;
    return top * (1.f - fy) + bot * fy;
}

__device__ __forceinline__ void sample_pair(const float* __restrict__ im,
                                            float cx, float cy, int W, int H,
                                            int lane, float& t0, float& t1) {
    float fix = floorf(cx), fiy = floorf(cy);
    float fx = cx - fix, fy = cy - fiy;
    int ix = (int)fix, iy = (int)fiy;
    int r = lane >> 2, cg = (lane & 3) << 1;
    bool fast = (ix >= 3) && (ix + 4 <= W - 1) && (iy >= 3) && (iy + 4 <= H - 1);
    if (fast) {
        const float* rp = im + (size_t)(iy - 3 + r) * W + (ix - 3 + cg);
        float w0 = __ldg(rp);
        float w1 = __ldg(rp + 1);
        float w2 = __shfl_down_sync(0xffffffffu, w0, 1);
        float ci0 = fmaf(fx, w1 - w0, w0);
        float ci1 = fmaf(fx, w2 - w1, w1);
        float cj0 = __shfl_down_sync(0xffffffffu, ci0, 4);
        float cj1 = __shfl_down_sync(0xffffffffu, ci1, 4);
        t0 = fmaf(fy, cj0 - ci0, ci0);
        t1 = fmaf(fy, cj1 - ci1, ci1);
    } else {
        t0 = bilinear_ref(im, cx + (float)(cg - 3), cy + (float)(r - 3), W, H);
        t1 = bilinear_ref(im, cx + (float)(cg - 2), cy + (float)(r - 3), W, H);
    }
}

// sorted-insert (ascending) into static-indexed 6-lists
#define INSERT6(d2, hv)                                                     \
    if ((d2) < d2k[KK - 1]) {                                               \
        d2k[KK - 1] = (d2); hk[KK - 1] = (hv);                              \
        _Pragma("unroll")                                                   \
        for (int _k = KK - 1; _k > 0; _k--) {                               \
            if (d2k[_k] < d2k[_k - 1]) {                                    \
                float _td = d2k[_k]; d2k[_k] = d2k[_k-1]; d2k[_k-1] = _td;  \
                float _th = hk[_k];  hk[_k]  = hk[_k-1];  hk[_k-1]  = _th;  \
            }                                                               \
        }                                                                   \
    }

// ---------------- kernel 0: zero accumulators ----------------
__global__ void zero_kernel() {
    int t = threadIdx.x;
    if (t < 8)   g_acc[t] = 0.f;
    if (t == 8)  g_cnt = 0;
    if (t < MAXB) {
        g_validn[t] = 0;
        g_nflag[t]  = 0;
        g_Sh[t] = 0.f;
        g_Sls[t] = 0.f;
        g_Ssl[t] = 0.f;
    }
}

// ---------------- kernel 1: per-point photo + geometry ----------------
__global__ void point_kernel(const float* __restrict__ lg,
                             const float* __restrict__ rg,
                             const float* __restrict__ kpl,
                             const float* __restrict__ kpr,
                             const float* __restrict__ scores,
                             const float* __restrict__ Q,
                             int B, int N, int H, int W) {
    __shared__ float sacc[6];
    __shared__ int   scnt;
    __shared__ float sVh;
    __shared__ int   sVn;
    int tid  = threadIdx.x;
    int warp = tid >> 5;
    int lane = tid & 31;
    if (tid < 6) sacc[tid] = 0.f;
    if (tid == 6) scnt = 0;
    if (tid == 7) { sVh = 0.f; sVn = 0; }
    __syncthreads();

    int total = B * N;
    int pFirst = blockIdx.x * 8;
    bool oneBatch = (pFirst / N) == (min(pFirst + 7, total - 1) / N);
    int p = pFirst + warp;
    if (p < total) {
        int b = p / N;
        float klx = __ldg(kpl + 2 * p),  kly = __ldg(kpl + 2 * p + 1);
        float krx = __ldg(kpr + 2 * p),  kry = __ldg(kpr + 2 * p + 1);
        float sc  = __ldg(scores + p);

        const float* Qb = Q + (size_t)b * 16;
        float disp = klx - krx;
        float p0 = Qb[0]  * klx + Qb[1]  * kly + Qb[2]  * disp + Qb[3];
        float p1 = Qb[4]  * klx + Qb[5]  * kly + Qb[6]  * disp + Qb[7];
        float p2 = Qb[8]  * klx + Qb[9]  * kly + Qb[10] * disp + Qb[11];
        float p3 = Qb[12] * klx + Qb[13] * kly + Qb[14] * disp + Qb[15];
        float Wc = fmaxf(p3, 1e-6f);
        float X = p0 / Wc, Y = p1 / Wc, Z = p2 / Wc;
        bool  valid = (Z > 100.f) && (Z < 30000.f) && (sc > 0.1f);
        float pmx = X / 1000.f;
        float hh  = Y / 1000.f;
        float pmz = Z / 1000.f;
        float sq  = pmx * pmx + pmz * pmz;

        if (lane == 0) {
            g_h[p]     = hh;
            g_valid[p] = valid ? 1 : 0;
            if (valid) { g_x[p] = pmx; g_z[p] = pmz; g_sq[p] = sq; }
            else       { g_x[p] = 0.f; g_z[p] = 0.f; g_sq[p] = 4e18f; }
        }

        const float* L = lg + (size_t)b * H * W;
        const float* R = rg + (size_t)b * H * W;
        float tl0, tl1, tr0, tr1;
        sample_pair(L, klx, kly, W, H, lane, tl0, tl1);
        sample_pair(R, krx, kry, W, H, lane, tr0, tr1);

        int r = lane >> 2;
        float a = 0.f;
        if (r < 7) {
            a = fabsf(tl0 - tr0);
            if ((lane & 3) < 3) a += fabsf(tl1 - tr1);
        }
        #pragma unroll
        for (int o = 16; o > 0; o >>= 1)
            a += __shfl_down_sync(0xffffffffu, a, o);

        float cl = __shfl_sync(0xffffffffu, tl1, 13);
        float cr = __shfl_sync(0xffffffffu, tr1, 13);

        if (lane == 0) {
            float diffm = a / 49.f;
            float isb   = (cl > 0.02f) ? 1.f : 0.f;
            float w     = sc * isb;
            float ydiff = fabsf(kly - kry);
            atomicAdd(&sacc[0], sc);
            atomicAdd(&sacc[1], ydiff * sc);
            atomicAdd(&sacc[2], ydiff);
            atomicAdd(&sacc[3], w);
            atomicAdd(&sacc[4], diffm * w);
            atomicAdd(&sacc[5], smooth_l1f(cl, cr, 1.f) * w);
            if (sc > 0.1f) atomicAdd(&scnt, 1);
            if (valid) {
                if (oneBatch) {
                    atomicAdd(&sVn, 1);
                    atomicAdd(&sVh, hh);
                } else {
                    atomicAdd(&g_validn[b], 1);
                    atomicAdd(&g_Sh[b], hh);
                }
            }
        }
    }
    __syncthreads();
    if (tid < 6) atomicAdd(&g_acc[tid], sacc[tid]);
    if (tid == 6 && scnt) atomicAdd(&g_cnt, scnt);
    if (tid == 7 && oneBatch && sVn) {
        int b0 = pFirst / N;
        atomicAdd(&g_validn[b0], sVn);
        atomicAdd(&g_Sh[b0], sVh);
    }
}

// ---------------- kernel 2a: per-batch bitonic sort by z ----------------
__global__ void sort_kernel(int N) {
    __shared__ float key[SORTN];
    __shared__ int   sidx[SORTN];
    int b = blockIdx.x;
    int tid = threadIdx.x;

    for (int i = tid; i < SORTN; i += 1024) {
        if (i < N) {
            int p = b * N + i;
            key[i]  = g_valid[p] ? g_z[p] : 1e30f;   // SORT KEY = z (cone geometry)
            sidx[i] = i;
        } else { key[i] = 3e30f; sidx[i] = 0; }
    }
    __syncthreads();

    for (int k = 2; k <= SORTN; k <<= 1) {
        for (int j = k >> 1; j > 0; j >>= 1) {
            for (int i = tid; i < SORTN; i += 1024) {
                int ixj = i ^ j;
                if (ixj > i) {
                    float a = key[i], c = key[ixj];
                    bool up = ((i & k) == 0);
                    if ((a > c) == up) {
                        key[i] = c; key[ixj] = a;
                        int t = sidx[i]; sidx[i] = sidx[ixj]; sidx[ixj] = t;
                    }
                }
            }
            __syncthreads();
        }
    }

    for (int i = tid; i < SORTN; i += 1024) {
        int o = b * SORTN + i;
        if (i < N) {
            int p = b * N + sidx[i];
            gs_z[o] = key[i];
            gs_x[o] = g_x[p];
            gs_h[o] = g_h[p];
            gs_q[o] = g_sq[p];
        } else {
            gs_z[o] = 3e30f; gs_x[o] = 0.f; gs_h[o] = 0.f; gs_q[o] = 4e18f;
        }
    }
}

// ---------------- kernel 2b: fixed-window 6-NN over z-sorted VALID prefix ----------------
__global__ void knn_window_kernel(int B, int N) {
    __shared__ float sx[SORTN], sz[SORTN], sh[SORTN], sq[SORTN];
    __shared__ float sls, ssl;
    int b   = blockIdx.y;
    int tid = threadIdx.x;      // 256
    int n   = blockIdx.x * 256 + tid;
    int base = b * SORTN;

    int nv = g_validn[b];
    for (int i = tid; i < nv; i += 256) {
        sx[i] = gs_x[base + i];
        sz[i] = gs_z[base + i];
        sh[i] = gs_h[base + i];
        sq[i] = gs_q[base + i];
    }
    if (tid == 0) { sls = 0.f; ssl = 0.f; }
    __syncthreads();

    bool active = (n < nv);

    float ls = 0.f, pensum = 0.f;
    if (active) {
        float xn = sx[n], zn = sz[n], hn = sh[n], sqn = sq[n];

        float d2k[KK], hk[KK];
        #pragma unroll
        for (int k = 0; k < KK; k++) { d2k[k] = 3.4e38f; hk[k] = 0.f; }

        // window clamped to the VALID prefix [0, nv)
        int lo = n - WIN;
        int hi = n + WIN;
        if (lo < 0)  { hi -= lo; lo = 0; }
        if (hi > nv) { lo -= (hi - nv); hi = nv; if (lo < 0) lo = 0; }

        #pragma unroll 4
        for (int j = lo; j < hi; j++) {
            float d2 = sqn + sq[j] - 2.f * (xn * sx[j] + zn * sz[j]);
            INSERT6(d2, sh[j]);
        }

        // exactness check (sorted coordinate = z) within valid prefix
        float thr = d2k[KK - 1] * 1.0001f + 1e-9f;
        bool bad = false;
        if (lo > 0)  { float dz = zn - sz[lo - 1]; if (dz * dz <= thr) bad = true; }
        if (hi < nv) { float dz = sz[hi] - zn;     if (dz * dz <= thr) bad = true; }

        if (bad) {
            int slot = atomicAdd(&g_nflag[b], 1);
            g_flag[base + slot] = n;
        } else {
            float lm = (hk[1] + hk[2] + hk[3] + hk[4] + hk[5]) / 5.f;
            ls = smooth_l1f(hn, lm, 0.01f);
            #pragma unroll
            for (int k = 1; k < KK; k++) {
                float nd = fmaxf(sqrtf(fmaxf(d2k[k], 1e-12f)), 0.001f);
                float s  = fabsf(hk[k] - hn) / nd;
                pensum  += fmaxf(s - 0.4f, 0.f);
            }
        }
    }

    #pragma unroll
    for (int o = 16; o > 0; o >>= 1) {
        ls     += __shfl_down_sync(0xffffffffu, ls, o);
        pensum += __shfl_down_sync(0xffffffffu, pensum, o);
    }
    if ((tid & 31) == 0) {
        atomicAdd(&sls, ls);
        atomicAdd(&ssl, pensum);
    }
    __syncthreads();
    if (tid == 0) {
        atomicAdd(&g_Sls[b], sls);
        atomicAdd(&g_Ssl[b], ssl);
    }
}

// ---------------- kernel 2c: exact brute fallback for flagged points ----------------
__global__ void knn_flag_kernel(int B, int N) {
    __shared__ float sls, ssl;
    int b    = blockIdx.y;
    int tid  = threadIdx.x;        // 256 = 8 warps
    int lane = tid & 31;
    int wIdx = blockIdx.x * 8 + (tid >> 5);
    int warpsPerBatch = gridDim.x * 8;
    int base = b * SORTN;
    int nf = g_nflag[b];
    int nv = g_validn[b];

    if (tid == 0) { sls = 0.f; ssl = 0.f; }
    __syncthreads();

    float lsAcc = 0.f, penAcc = 0.f;
    for (int f = wIdx; f < nf; f += warpsPerBatch) {
        int n = g_flag[base + f];
        float xn = gs_x[base + n], zn = gs_z[base + n];
        float hn = gs_h[base + n], sqn = gs_q[base + n];

        float d2k[KK], hk[KK];
        #pragma unroll
        for (int k = 0; k < KK; k++) { d2k[k] = 3.4e38f; hk[k] = 0.f; }

        for (int j = lane; j < nv; j += 32) {
            float d2 = sqn + __ldg(gs_q + base + j)
                     - 2.f * (xn * __ldg(gs_x + base + j) + zn * __ldg(gs_z + base + j));
            float hv = __ldg(gs_h + base + j);
            INSERT6(d2, hv);
        }

        // warp merge: extract 6 global minima from 32 sorted per-lane lists
        float md[KK], mh[KK];
        #pragma unroll
        for (int r = 0; r < KK; r++) {
            float v  = d2k[0];
            float mv = v;
            #pragma unroll
            for (int o = 16; o > 0; o >>= 1)
                mv = fminf(mv, __shfl_xor_sync(0xffffffffu, mv, o));
            unsigned msk = __ballot_sync(0xffffffffu, v == mv);
            int src = __ffs(msk) - 1;
            float hh0 = hk[0];
            float mhh = __shfl_sync(0xffffffffu, hh0, src);
            if (lane == src) {
                #pragma unroll
                for (int k = 0; k < KK - 1; k++) { d2k[k] = d2k[k + 1]; hk[k] = hk[k + 1]; }
                d2k[KK - 1] = 3.4e38f; hk[KK - 1] = 0.f;
            }
            md[r] = mv; mh[r] = mhh;
        }

        if (lane == 0) {
            float lm = (mh[1] + mh[2] + mh[3] + mh[4] + mh[5]) / 5.f;
            lsAcc += smooth_l1f(hn, lm, 0.01f);
            #pragma unroll
            for (int k = 1; k < KK; k++) {
                float nd = fmaxf(sqrtf(fmaxf(md[k], 1e-12f)), 0.001f);
                float s  = fabsf(mh[k] - hn) / nd;
                penAcc  += fmaxf(s - 0.4f, 0.f);
            }
        }
    }
    if (lane == 0 && (lsAcc != 0.f || penAcc != 0.f)) {
        atomicAdd(&sls, lsAcc);
        atomicAdd(&ssl, penAcc);
    }
    __syncthreads();
    if (tid == 0 && (sls != 0.f || ssl != 0.f)) {
        atomicAdd(&g_Sls[b], sls);
        atomicAdd(&g_Ssl[b], ssl);
    }
}

// ---------------- fallback brute-force knn (N > SORTN only) ----------------
__global__ void knn_brute_kernel(int B, int N) {
    __shared__ float4 tile[256];
    __shared__ float  sls, ssl;
    int b = blockIdx.y;
    int n = blockIdx.x * blockDim.x + threadIdx.x;
    int rowBase = b * N;

    bool active = false;
    float xn = 0.f, zn = 0.f, sqn = 0.f, hn = 0.f;
    if (n < N) {
        int p = rowBase + n;
        active = (g_valid[p] != 0);
        xn = g_x[p]; zn = g_z[p]; sqn = g_sq[p]; hn = g_h[p];
    }
    float d2k[KK], hk[KK];
    #pragma unroll
    for (int k = 0; k < KK; k++) { d2k[k] = 3.4e38f; hk[k] = 0.f; }
    if (threadIdx.x == 0) { sls = 0.f; ssl = 0.f; }

    for (int basem = 0; basem < N; basem += 256) {
        int m = basem + threadIdx.x;
        if (m < N) {
            int q = rowBase + m;
            tile[threadIdx.x] = make_float4(g_x[q], g_z[q], g_h[q], g_sq[q]);
        }
        __syncthreads();
        int cnt = min(256, N - basem);
        if (active) {
            for (int j = 0; j < cnt; j++) {
                float4 v = tile[j];
                float d2 = sqn + v.w - 2.f * (xn * v.x + zn * v.y);
                INSERT6(d2, v.z);
            }
        }
        __syncthreads();
    }

    float ls = 0.f, pensum = 0.f;
    if (active) {
        float lm = (hk[1] + hk[2] + hk[3] + hk[4] + hk[5]) / 5.f;
        ls = smooth_l1f(hn, lm, 0.01f);
        #pragma unroll
        for (int k = 1; k < KK; k++) {
            float nd = fmaxf(sqrtf(fmaxf(d2k[k], 1e-12f)), 0.001f);
            float s  = fabsf(hk[k] - hn) / nd;
            pensum  += fmaxf(s - 0.4f, 0.f);
        }
    }
    #pragma unroll
    for (int o = 16; o > 0; o >>= 1) {
        ls     += __shfl_down_sync(0xffffffffu, ls, o);
        pensum += __shfl_down_sync(0xffffffffu, pensum, o);
    }
    if ((threadIdx.x & 31) == 0) { atomicAdd(&sls, ls); atomicAdd(&ssl, pensum); }
    __syncthreads();
    if (threadIdx.x == 0) { atomicAdd(&g_Sls[b], sls); atomicAdd(&g_Ssl[b], ssl); }
}

// ---------------- kernel 3: finalize ----------------
__global__ void final_kernel(float* __restrict__ out, int B, int N) {
    int t = threadIdx.x;
    float s_ls = 0.f, s_sl = 0.f, s_lz = 0.f, s_ok = 0.f;
    for (int b = t; b < B; b += 32) {
        int nvi  = g_validn[b];
        float nv = (float)max(nvi, 1);
        float ok = (nvi >= 10) ? 1.f : 0.f;
        s_ls += ok * (g_Sls[b] / nv);
        s_sl += ok * (g_Ssl[b] / (nv * (float)KNN));
        s_lz += ok * fabsf(g_Sh[b] / nv);
        s_ok += ok;
    }
    #pragma unroll
    for (int o = 16; o > 0; o >>= 1) {
        s_ls += __shfl_down_sync(0xffffffffu, s_ls, o);
        s_sl += __shfl_down_sync(0xffffffffu, s_sl, o);
        s_lz += __shfl_down_sync(0xffffffffu, s_lz, o);
        s_ok += __shfl_down_sync(0xffffffffu, s_ok, o);
    }
    if (t == 0) {
        float ws = g_acc[0];
        float l_epi = (ws > 0.0001f) ? (g_acc[1] / fmaxf(ws, 1e-12f))
                                     : (g_acc[2] / (float)(B * N));
        float wsum = g_acc[3];
        float safe = fmaxf(wsum, 1e-12f);
        float l_masked    = (wsum > 0.0001f) ? (g_acc[4] / safe) : 0.f;
        float l_intensity = (wsum > 0.0001f) ? (g_acc[5] / safe) : 0.f;

        float nb = fmaxf(s_ok, 1.f);
        bool gate = (g_cnt >= 10) && (s_ok > 0.f);

        out[0] = l_masked + l_intensity;
        out[1] = l_epi;
        out[2] = gate ? (s_ls / nb) : 0.f;
        out[3] = gate ? (s_sl / nb) : 0.f;
        out[4] = gate ? (s_lz / nb) : 0.f;
    }
}

// ---------------- launch ----------------
extern "C" void kernel_launch(void* const* d_in, const int* in_sizes, int n_in,
                              void* d_out, int out_size) {
    const float* lg     = (const float*)d_in[0];
    const float* rg     = (const float*)d_in[1];
    const float* kpl    = (const float*)d_in[2];
    const float* kpr    = (const float*)d_in[3];
    const float* scores = (const float*)d_in[4];
    const float* Q      = (const float*)d_in[5];
    float* out = (float*)d_out;

    int B = in_sizes[5] / 16;
    int N = in_sizes[4] / B;
    int HW = in_sizes[0] / B;
    int W = 1280, H = HW / W;
    if (H * W != HW) { W = 1280; H = HW / W; }
    int total = B * N;

    zero_kernel<<<1, 256>>>();

    int blocks1 = (total + 7) / 8;
    point_kernel<<<blocks1, 256>>>(lg, rg, kpl, kpr, scores, Q, B, N, H, W);

    if (N <= SORTN && B <= MAXB) {
        sort_kernel<<<B, 1024>>>(N);
        dim3 g2((N + 255) / 256, B);
        knn_window_kernel<<<g2, 256>>>(B, N);
        dim3 g3(8, B);
        knn_flag_kernel<<<g3, 256>>>(B, N);
    } else {
        dim3 g2((N + 255) / 256, B);
        knn_brute_kernel<<<g2, 256>>>(B, N);
    }

    final_kernel<<<1, 32>>>(out, B, N);
}